// round 4
// baseline (speedup 1.0000x reference)
#include <cuda_runtime.h>
#include <cuda_bf16.h>
#include <math_constants.h>
#include <stdint.h>

// Problem dims
#define B_   4
#define T_   1024
#define H_   12
#define C_   4096
#define DK_  64
#define DV_  64
#define N_   (B_*T_)      // 4096
#define DIM_ (H_*DK_)     // 768

// GEMM config
#define KP   192          // packed K (bf16 split: [xh|xh|xl] . [eh|el|eh])
#define TM   128          // rows per CTA
#define TCC  64           // codes per iteration
#define NCT  (C_/TCC)     // 64
#define SA   400          // smem row stride in BYTES (200 bf16; 400%128=16 -> ldmatrix conflict-free)
#define A_BYTES      (TM*SA)        // 51200
#define B_TILE_BYTES (TCC*SA)       // 25600
#define W_SEL 3e-4f       // ambiguity window (~4x worst-case approx error)

// smem offsets
#define OFF_A   0
#define OFF_B   51200     // two B tiles
#define OFF_PM1 102400    // float[128]
#define OFF_PM2 102912    // float[128]
#define OFF_PI1 103424    // int[128]
#define SMEM_SZ 103936

// Device scratch (no allocations allowed)
__device__ __align__(1024) __nv_bfloat16 g_A[(size_t)H_*N_*KP];
__device__ __align__(1024) __nv_bfloat16 g_B[(size_t)H_*C_*KP];
__device__ float g_e2[H_*C_];
__device__ int   g_idx[H_*N_];
__device__ int   g_list[H_*N_];
__device__ int   g_cnt;

// ---------------- helpers ----------------
__device__ __forceinline__ uint32_t smem_u32(const void* p) {
    uint32_t a;
    asm("{ .reg .u64 t; cvta.to.shared.u64 t, %1; cvt.u32.u64 %0, t; }" : "=r"(a) : "l"(p));
    return a;
}
__device__ __forceinline__ void cpa16(uint32_t dst, const void* src) {
    asm volatile("cp.async.cg.shared.global [%0], [%1], 16;" :: "r"(dst), "l"(src));
}
__device__ __forceinline__ void cpa_commit() { asm volatile("cp.async.commit_group;" ::: "memory"); }
__device__ __forceinline__ void cpa_wait0()  { asm volatile("cp.async.wait_group 0;" ::: "memory"); }
__device__ __forceinline__ void cpa_wait1()  { asm volatile("cp.async.wait_group 1;" ::: "memory"); }

__device__ __forceinline__ void ldsm4(uint32_t* r, uint32_t addr) {
    asm volatile("ldmatrix.sync.aligned.m8n8.x4.shared.b16 {%0,%1,%2,%3}, [%4];"
                 : "=r"(r[0]), "=r"(r[1]), "=r"(r[2]), "=r"(r[3]) : "r"(addr));
}
__device__ __forceinline__ void mma16816(float* d, const uint32_t* a, const uint32_t* b) {
    asm volatile("mma.sync.aligned.m16n8k16.row.col.f32.bf16.bf16.f32 "
                 "{%0,%1,%2,%3}, {%4,%5,%6,%7}, {%8,%9}, {%0,%1,%2,%3};"
                 : "+f"(d[0]), "+f"(d[1]), "+f"(d[2]), "+f"(d[3])
                 : "r"(a[0]), "r"(a[1]), "r"(a[2]), "r"(a[3]), "r"(b[0]), "r"(b[1]));
}

// top-2 merge (commutative, index tie-break -> deterministic)
__device__ __forceinline__ void merge2(float& m1, int& i1, float& m2,
                                       float om1, int oi1, float om2) {
    if (om1 < m1 || (om1 == m1 && oi1 < i1)) {
        m2 = fminf(m1, om2); m1 = om1; i1 = oi1;
    } else {
        m2 = fminf(m2, om1);
    }
}

// ---------------------------------------------------------------------------
// Prep kernels
// ---------------------------------------------------------------------------
__global__ void e2_kernel(const float* __restrict__ ke) {
    int idx = blockIdx.x * blockDim.x + threadIdx.x;
    if (idx == 0) g_cnt = 0;
    if (idx >= H_ * C_) return;
    const float* p = ke + (size_t)idx * DK_;
    float s = 0.f;
#pragma unroll
    for (int d = 0; d < DK_; d++) s = __fmaf_rn(p[d], p[d], s);
    g_e2[idx] = s;
}

__global__ void prep_a(const float* __restrict__ x) {
    int lin = blockIdx.x * blockDim.x + threadIdx.x;      // H*N*64
    if (lin >= H_ * N_ * DK_) return;
    int d = lin & 63; int hn = lin >> 6;
    int n = hn & (N_ - 1); int h = hn >> 12;
    float v = x[(size_t)n * DIM_ + h * DK_ + d];
    __nv_bfloat16 hi = __float2bfloat16(v);
    __nv_bfloat16 lo = __float2bfloat16(v - __bfloat162float(hi));
    size_t base = (size_t)hn * KP;
    g_A[base + d] = hi; g_A[base + 64 + d] = hi; g_A[base + 128 + d] = lo;
}

__global__ void prep_b(const float* __restrict__ ke) {
    int lin = blockIdx.x * blockDim.x + threadIdx.x;      // H*C*64
    if (lin >= H_ * C_ * DK_) return;
    int d = lin & 63; int hc = lin >> 6;
    float v = ke[(size_t)hc * DK_ + d];
    __nv_bfloat16 hi = __float2bfloat16(v);
    __nv_bfloat16 lo = __float2bfloat16(v - __bfloat162float(hi));
    size_t base = (size_t)hc * KP;
    g_B[base + d] = hi; g_B[base + 64 + d] = lo; g_B[base + 128 + d] = hi;
}

// ---------------------------------------------------------------------------
// Main: bf16 HMMA GEMM (K=192) + top-2 argmin + ambiguity flagging
// grid = (N_/TM, H_), block = 128 (4 warps, 2x2 warp grid, 64x32 per warp)
// ---------------------------------------------------------------------------
__global__ __launch_bounds__(128, 2)
void hmma_argmin_kernel() {
    extern __shared__ char smem[];
    const uint32_t sb = smem_u32(smem);
    const int tid = threadIdx.x, lane = tid & 31, wid = tid >> 5;
    const int wm = wid >> 1, wn = wid & 1;
    const int h = blockIdx.y, ntb = blockIdx.x;

    float* pm1 = (float*)(smem + OFF_PM1);
    float* pm2 = (float*)(smem + OFF_PM2);
    int*   pi1 = (int*)  (smem + OFF_PI1);

    const __nv_bfloat16* Ag = g_A + (size_t)(h * N_ + ntb * TM) * KP;
    const __nv_bfloat16* Bg = g_B + (size_t)h * C_ * KP;
    const float* e2h = g_e2 + h * C_;

    // Prologue: A tile + B tile 0  (group 0)
#pragma unroll 4
    for (int m = tid; m < TM * 24; m += 128)
        cpa16(sb + OFF_A + (m / 24) * SA + (m % 24) * 16, Ag + m * 8);
#pragma unroll 4
    for (int m = tid; m < TCC * 24; m += 128)
        cpa16(sb + OFF_B + (m / 24) * SA + (m % 24) * 16, Bg + m * 8);
    cpa_commit();

    // ldmatrix per-thread base addresses
    // A: x4 tiles (rows0-7,k0-7)(rows8-15,k0-7)(rows0-7,k8-15)(rows8-15,k8-15)
    const uint32_t aAddr = sb + OFF_A +
        (uint32_t)((wm * 64 + (lane & 15)) * SA + (lane >> 4) * 16);
    // B: x4 tiles cover 2 n-tiles: (n0-7,k0-7)(n0-7,k8-15)(n8-15,k0-7)(n8-15,k8-15)
    const uint32_t bAddrBase =
        (uint32_t)((wn * 32 + (lane & 7) + ((lane >> 4) & 1) * 8) * SA +
                   ((lane >> 3) & 1) * 16);

    float m1[8], m2[8]; int i1[8];
#pragma unroll
    for (int q = 0; q < 8; q++) { m1[q] = CUDART_INF_F; m2[q] = CUDART_INF_F; i1[q] = 0; }

    for (int ct = 0; ct < NCT; ct++) {
        // prefetch next B tile into the other buffer
        if (ct + 1 < NCT) {
            const __nv_bfloat16* Bt = Bg + (size_t)(ct + 1) * TCC * KP;
            uint32_t dstb = sb + OFF_B + ((ct + 1) & 1) * B_TILE_BYTES;
#pragma unroll 4
            for (int m = tid; m < TCC * 24; m += 128)
                cpa16(dstb + (m / 24) * SA + (m % 24) * 16, Bt + m * 8);
            cpa_commit();
            cpa_wait1();          // current tile's group done, next in flight
        } else {
            cpa_wait0();
        }
        __syncthreads();

        // e2 for this thread's 8 columns (hidden under the mma loop)
        const int cth = ct * TCC + wn * 32 + (lane & 3) * 2;
        float e2v[4][2];
#pragma unroll
        for (int nt = 0; nt < 4; nt++) {
            e2v[nt][0] = __ldg(e2h + cth + nt * 8);
            e2v[nt][1] = __ldg(e2h + cth + nt * 8 + 1);
        }

        float acc[4][4][4];
#pragma unroll
        for (int mt = 0; mt < 4; mt++)
#pragma unroll
            for (int nt = 0; nt < 4; nt++)
#pragma unroll
                for (int v = 0; v < 4; v++) acc[mt][nt][v] = 0.f;

        const uint32_t bAddr = sb + OFF_B + (ct & 1) * B_TILE_BYTES + bAddrBase;

#pragma unroll
        for (int ks = 0; ks < 12; ks++) {
            uint32_t a[4][4], b[2][4];
#pragma unroll
            for (int mt = 0; mt < 4; mt++)
                ldsm4(a[mt], aAddr + mt * (16 * SA) + ks * 32);
#pragma unroll
            for (int np = 0; np < 2; np++)
                ldsm4(b[np], bAddr + np * (16 * SA) + ks * 32);
#pragma unroll
            for (int mt = 0; mt < 4; mt++)
#pragma unroll
                for (int nt = 0; nt < 4; nt++)
                    mma16816(acc[mt][nt], a[mt], &b[nt >> 1][(nt & 1) * 2]);
        }

        // epilogue: s = e2 - 2*dot, running top-2 (c ascending per state)
#pragma unroll
        for (int mt = 0; mt < 4; mt++)
#pragma unroll
            for (int nt = 0; nt < 4; nt++)
#pragma unroll
                for (int v = 0; v < 4; v++) {
                    float s = fmaf(-2.f, acc[mt][nt][v], e2v[nt][v & 1]);
                    int c = cth + nt * 8 + (v & 1);
                    int q = mt * 2 + (v >> 1);
                    if (s < m1[q])      { m2[q] = m1[q]; m1[q] = s; i1[q] = c; }
                    else if (s < m2[q]) { m2[q] = s; }
                }
        __syncthreads();   // before next prefetch overwrites buf[ct&1]
    }

    // quad reduce (lanes sharing lane>>2 cover disjoint columns of same rows)
#pragma unroll
    for (int q = 0; q < 8; q++) {
#pragma unroll
        for (int d = 1; d <= 2; d <<= 1) {
            float om1 = __shfl_xor_sync(0xffffffffu, m1[q], d);
            int   oi1 = __shfl_xor_sync(0xffffffffu, i1[q], d);
            float om2 = __shfl_xor_sync(0xffffffffu, m2[q], d);
            merge2(m1[q], i1[q], m2[q], om1, oi1, om2);
        }
    }

    // cross-warp merge over wn (two warps share each row range)
    if (wn == 1 && (lane & 3) == 0) {
#pragma unroll
        for (int q = 0; q < 8; q++) {
            int r = wm * 64 + (q >> 1) * 16 + (q & 1) * 8 + (lane >> 2);
            pm1[r] = m1[q]; pm2[r] = m2[q]; pi1[r] = i1[q];
        }
    }
    __syncthreads();
    if (wn == 0 && (lane & 3) == 0) {
#pragma unroll
        for (int q = 0; q < 8; q++) {
            int r = wm * 64 + (q >> 1) * 16 + (q & 1) * 8 + (lane >> 2);
            merge2(m1[q], i1[q], m2[q], pm1[r], pi1[r], pm2[r]);
            int row = h * N_ + ntb * TM + r;
            g_idx[row] = i1[q];
            if (!(m2[q] - m1[q] > W_SEL)) {
                int p = atomicAdd(&g_cnt, 1);
                g_list[p] = row;
            }
        }
    }
}

// ---------------------------------------------------------------------------
// Cleanup: exact fp32 replay (bit-identical to the reference-matching formula)
// ---------------------------------------------------------------------------
__global__ void cleanup_kernel(const float* __restrict__ x,
                               const float* __restrict__ ke) {
    __shared__ float xs[DK_];
    __shared__ float rv[256];
    __shared__ int   ri[256];
    const int tid = threadIdx.x;
    for (int e = blockIdx.x; e < g_cnt; e += gridDim.x) {
        int row = g_list[e];
        int h = row >> 12, n = row & (N_ - 1);
        if (tid < DK_) xs[tid] = x[(size_t)n * DIM_ + h * DK_ + tid];
        __syncthreads();
        float x2 = 0.f;
#pragma unroll
        for (int d = 0; d < DK_; d++) x2 = __fmaf_rn(xs[d], xs[d], x2);
        const float* keh = ke + (size_t)h * C_ * DK_;
        const float* e2h = g_e2 + h * C_;
        float bv = CUDART_INF_F; int bi = 0;
        for (int c = tid; c < C_; c += 256) {
            const float* kp = keh + (size_t)c * DK_;
            float dot = 0.f;
#pragma unroll
            for (int d = 0; d < DK_; d++) dot = __fmaf_rn(xs[d], kp[d], dot);
            float t = __fmaf_rn(-2.0f, dot, x2);
            float s = __fadd_rn(t, e2h[c]);
            if (s < bv) { bv = s; bi = c; }
        }
        rv[tid] = bv; ri[tid] = bi;
        __syncthreads();
        if (tid == 0) {
            float b = rv[0]; int bi2 = ri[0];
            for (int t = 1; t < 256; t++) {
                float v = rv[t]; int c = ri[t];
                if (v < b || (v == b && c < bi2)) { b = v; bi2 = c; }
            }
            g_idx[row] = bi2;
        }
        __syncthreads();
    }
}

// ---------------------------------------------------------------------------
// Gather
// ---------------------------------------------------------------------------
__global__ void gather_kernel(const float* __restrict__ vals,
                              float* __restrict__ out) {
    int lin = blockIdx.x * blockDim.x + threadIdx.x;   // H*N*16 float4s
    if (lin >= H_ * N_ * 16) return;
    int v4 = lin & 15; int hn = lin >> 4;
    int n = hn & (N_ - 1); int h = hn >> 12;
    int c = g_idx[hn];
    float4 v = *(const float4*)(vals + ((size_t)h * C_ + c) * DV_ + v4 * 4);
    *(float4*)(out + (size_t)n * DIM_ + h * DV_ + v4 * 4) = v;
}

// ---------------------------------------------------------------------------
extern "C" void kernel_launch(void* const* d_in, const int* in_sizes, int n_in,
                              void* d_out, int out_size) {
    const float* x    = (const float*)d_in[0];
    const float* ke   = (const float*)d_in[2];
    const float* vals = (const float*)d_in[3];
    float* out = (float*)d_out;

    cudaFuncSetAttribute(hmma_argmin_kernel,
                         cudaFuncAttributeMaxDynamicSharedMemorySize, SMEM_SZ);

    e2_kernel<<<(H_ * C_ + 255) / 256, 256>>>(ke);
    prep_a<<<(H_ * N_ * DK_) / 256, 256>>>(x);
    prep_b<<<(H_ * C_ * DK_) / 256, 256>>>(ke);

    dim3 grid(N_ / TM, H_);
    hmma_argmin_kernel<<<grid, 128, SMEM_SZ>>>();

    cleanup_kernel<<<296, 256>>>(x, ke);
    gather_kernel<<<(H_ * N_ * 16) / 256, 256>>>(vals, out);
}

// round 5
// speedup vs baseline: 3.4185x; 3.4185x over previous
#include <cuda_runtime.h>
#include <cuda_bf16.h>
#include <math_constants.h>
#include <stdint.h>

// Problem dims
#define B_   4
#define T_   1024
#define H_   12
#define C_   4096
#define DK_  64
#define DV_  64
#define N_   (B_*T_)      // 4096
#define DIM_ (H_*DK_)     // 768

// GEMM config
#define KP   192          // packed K (bf16 split: [xh|xh|xl] . [eh|el|eh])
#define TM   128          // rows per CTA
#define TCC  64           // codes per iteration
#define NCT  (C_/TCC)     // 64
#define SA   400          // smem row stride bytes (conflict-free ldmatrix)
#define B_TILE_BYTES (TCC*SA)     // 25600
#define W_SEL 3e-4f       // ambiguity window (>= ~10x approx-error bound)

// smem offsets (main kernel)
#define OFF_A   0
#define OFF_B   51200             // 2 buffers of B
#define OFF_P   102400            // pm1,pm2,pm3,pi1,pi2 : 5 * 128 * 4
#define SMEM_SZ 104960

// Device scratch
__device__ __align__(1024) __nv_bfloat16 g_A[(size_t)H_*N_*KP];
__device__ __align__(1024) __nv_bfloat16 g_B[(size_t)H_*C_*KP];
__device__ float g_e2[H_*C_];
__device__ int   g_idx[H_*N_];
__device__ int   g_listA[H_*N_];   // candidate rows
__device__ int   g_listA2[H_*N_];  // their i2
__device__ int   g_listB[H_*N_];   // full-replay rows
__device__ int   g_cntA;
__device__ int   g_cntB;

// ---------------- helpers ----------------
__device__ __forceinline__ uint32_t smem_u32(const void* p) {
    uint32_t a;
    asm("{ .reg .u64 t; cvta.to.shared.u64 t, %1; cvt.u32.u64 %0, t; }" : "=r"(a) : "l"(p));
    return a;
}
__device__ __forceinline__ void cpa16(uint32_t dst, const void* src) {
    asm volatile("cp.async.cg.shared.global [%0], [%1], 16;" :: "r"(dst), "l"(src));
}
__device__ __forceinline__ void cpa_commit() { asm volatile("cp.async.commit_group;" ::: "memory"); }
__device__ __forceinline__ void cpa_wait0()  { asm volatile("cp.async.wait_group 0;" ::: "memory"); }
__device__ __forceinline__ void cpa_wait1()  { asm volatile("cp.async.wait_group 1;" ::: "memory"); }

__device__ __forceinline__ void ldsm4(uint32_t* r, uint32_t addr) {
    asm volatile("ldmatrix.sync.aligned.m8n8.x4.shared.b16 {%0,%1,%2,%3}, [%4];"
                 : "=r"(r[0]), "=r"(r[1]), "=r"(r[2]), "=r"(r[3]) : "r"(addr));
}
__device__ __forceinline__ void mma16816(float* d, const uint32_t* a, const uint32_t* b) {
    asm volatile("mma.sync.aligned.m16n8k16.row.col.f32.bf16.bf16.f32 "
                 "{%0,%1,%2,%3}, {%4,%5,%6,%7}, {%8,%9}, {%0,%1,%2,%3};"
                 : "+f"(d[0]), "+f"(d[1]), "+f"(d[2]), "+f"(d[3])
                 : "r"(a[0]), "r"(a[1]), "r"(a[2]), "r"(a[3]), "r"(b[0]), "r"(b[1]));
}

// merge two top-3 partial states (values m1<=m2<=m3, indices for m1,m2)
__device__ __forceinline__ void merge3(float& m1, int& i1, float& m2, int& i2, float& m3,
                                       float bm1, int bi1, float bm2, int bi2, float bm3) {
    if (bm1 < m1 || (bm1 == m1 && bi1 < i1)) {
        // swap so (m1,i1,...) is the smaller-head set
        float t; int ti;
        t = m1; m1 = bm1; bm1 = t;  ti = i1; i1 = bi1; bi1 = ti;
        t = m2; m2 = bm2; bm2 = t;  ti = i2; i2 = bi2; bi2 = ti;
        t = m3; m3 = bm3; bm3 = t;
    }
    // head = (m1,i1). remaining: m2(i2), m3, bm1(bi1), bm2(bi2), bm3
    if (bm1 < m2 || (bm1 == m2 && bi1 < i2)) {
        m3 = fminf(m2, bm2);
        m2 = bm1; i2 = bi1;
    } else {
        m3 = fminf(m3, bm1);
    }
}

// ---------------------------------------------------------------------------
// Prep kernels
// ---------------------------------------------------------------------------
__global__ void e2_kernel(const float* __restrict__ ke) {
    int idx = blockIdx.x * blockDim.x + threadIdx.x;
    if (idx == 0) { g_cntA = 0; g_cntB = 0; }
    if (idx >= H_ * C_) return;
    const float* p = ke + (size_t)idx * DK_;
    float s = 0.f;
#pragma unroll
    for (int d = 0; d < DK_; d++) s = __fmaf_rn(p[d], p[d], s);
    g_e2[idx] = s;
}

__global__ void prep_a(const float* __restrict__ x) {
    int lin = blockIdx.x * blockDim.x + threadIdx.x;      // H*N*64
    if (lin >= H_ * N_ * DK_) return;
    int d = lin & 63; int hn = lin >> 6;
    int n = hn & (N_ - 1); int h = hn >> 12;
    float v = x[(size_t)n * DIM_ + h * DK_ + d];
    __nv_bfloat16 hi = __float2bfloat16(v);
    __nv_bfloat16 lo = __float2bfloat16(v - __bfloat162float(hi));
    size_t base = (size_t)hn * KP;
    g_A[base + d] = hi; g_A[base + 64 + d] = hi; g_A[base + 128 + d] = lo;
}

__global__ void prep_b(const float* __restrict__ ke) {
    int lin = blockIdx.x * blockDim.x + threadIdx.x;      // H*C*64
    if (lin >= H_ * C_ * DK_) return;
    int d = lin & 63; int hc = lin >> 6;
    float v = ke[(size_t)hc * DK_ + d];
    __nv_bfloat16 hi = __float2bfloat16(v);
    __nv_bfloat16 lo = __float2bfloat16(v - __bfloat162float(hi));
    size_t base = (size_t)hc * KP;
    g_B[base + d] = hi; g_B[base + 64 + d] = lo; g_B[base + 128 + d] = hi;
}

// ---------------------------------------------------------------------------
// Main: bf16 HMMA GEMM (K=192) + top-3 argmin + classification
// grid = (N_/TM, H_), block = 256 (8 warps, 4(wm) x 2(wn), warp tile 32x32)
// ---------------------------------------------------------------------------
__global__ __launch_bounds__(256, 2)
void hmma_argmin_kernel() {
    extern __shared__ char smem[];
    const uint32_t sb = smem_u32(smem);
    const int tid = threadIdx.x, lane = tid & 31, wid = tid >> 5;
    const int wm = wid >> 1, wn = wid & 1;
    const int h = blockIdx.y, ntb = blockIdx.x;

    float* pm1 = (float*)(smem + OFF_P);
    float* pm2 = pm1 + 128;
    float* pm3 = pm2 + 128;
    int*   pi1 = (int*)(pm3 + 128);
    int*   pi2 = pi1 + 128;

    const __nv_bfloat16* Ag = g_A + (size_t)(h * N_ + ntb * TM) * KP;
    const __nv_bfloat16* Bg = g_B + (size_t)h * C_ * KP;
    const float* e2h = g_e2 + h * C_;

    // Prologue: A tile (128 rows x 24 chunks) + B tile 0 (64 x 24)
#pragma unroll 4
    for (int m = tid; m < TM * 24; m += 256)
        cpa16(sb + OFF_A + (m / 24) * SA + (m % 24) * 16, Ag + m * 8);
#pragma unroll 2
    for (int m = tid; m < TCC * 24; m += 256)
        cpa16(sb + OFF_B + (m / 24) * SA + (m % 24) * 16, Bg + m * 8);
    cpa_commit();

    // ldmatrix base addresses (warp tile 32 rows x 32 cols)
    const uint32_t aAddr = sb + OFF_A +
        (uint32_t)((wm * 32 + (lane & 15)) * SA + (lane >> 4) * 16);
    const uint32_t bAddrBase =
        (uint32_t)((wn * 32 + (lane & 7) + ((lane >> 4) & 1) * 8) * SA +
                   ((lane >> 3) & 1) * 16);

    // per-thread top-3 state for 4 row slots q = mt*2 + (v>>1)
    float m1[4], m2[4], m3[4]; int i1[4], i2[4];
#pragma unroll
    for (int q = 0; q < 4; q++) {
        m1[q] = CUDART_INF_F; m2[q] = CUDART_INF_F; m3[q] = CUDART_INF_F;
        i1[q] = 0; i2[q] = 0;
    }

    for (int ct = 0; ct < NCT; ct++) {
        if (ct + 1 < NCT) {
            const __nv_bfloat16* Bt = Bg + (size_t)(ct + 1) * TCC * KP;
            uint32_t dstb = sb + OFF_B + ((ct + 1) & 1) * B_TILE_BYTES;
#pragma unroll 2
            for (int m = tid; m < TCC * 24; m += 256)
                cpa16(dstb + (m / 24) * SA + (m % 24) * 16, Bt + m * 8);
            cpa_commit();
            cpa_wait1();
        } else {
            cpa_wait0();
        }
        __syncthreads();

        const int cth = ct * TCC + wn * 32 + (lane & 3) * 2;
        float e2v[4][2];
#pragma unroll
        for (int nt = 0; nt < 4; nt++) {
            e2v[nt][0] = __ldg(e2h + cth + nt * 8);
            e2v[nt][1] = __ldg(e2h + cth + nt * 8 + 1);
        }

        float acc[2][4][4];
#pragma unroll
        for (int mt = 0; mt < 2; mt++)
#pragma unroll
            for (int nt = 0; nt < 4; nt++)
#pragma unroll
                for (int v = 0; v < 4; v++) acc[mt][nt][v] = 0.f;

        const uint32_t bAddr = sb + OFF_B + (ct & 1) * B_TILE_BYTES + bAddrBase;

#pragma unroll
        for (int ks = 0; ks < 12; ks++) {
            uint32_t a[2][4], b[2][4];
#pragma unroll
            for (int mt = 0; mt < 2; mt++)
                ldsm4(a[mt], aAddr + mt * (16 * SA) + ks * 32);
#pragma unroll
            for (int np = 0; np < 2; np++)
                ldsm4(b[np], bAddr + np * (16 * SA) + ks * 32);
#pragma unroll
            for (int mt = 0; mt < 2; mt++)
#pragma unroll
                for (int nt = 0; nt < 4; nt++)
                    mma16816(acc[mt][nt], a[mt], &b[nt >> 1][(nt & 1) * 2]);
        }

        // epilogue: s = e2 - 2*dot, running top-3 (c ascending per slot)
#pragma unroll
        for (int mt = 0; mt < 2; mt++)
#pragma unroll
            for (int nt = 0; nt < 4; nt++)
#pragma unroll
                for (int v = 0; v < 4; v++) {
                    float s = fmaf(-2.f, acc[mt][nt][v], e2v[nt][v & 1]);
                    int c = cth + nt * 8 + (v & 1);
                    int q = mt * 2 + (v >> 1);
                    if (s < m1[q]) {
                        m3[q] = m2[q]; m2[q] = m1[q]; i2[q] = i1[q];
                        m1[q] = s; i1[q] = c;
                    } else if (s < m2[q]) {
                        m3[q] = m2[q]; m2[q] = s; i2[q] = c;
                    } else if (s < m3[q]) {
                        m3[q] = s;
                    }
                }
        __syncthreads();
    }

    // quad reduce (lanes xor 1,2 cover disjoint columns, same rows)
#pragma unroll
    for (int q = 0; q < 4; q++) {
#pragma unroll
        for (int d = 1; d <= 2; d <<= 1) {
            float bm1 = __shfl_xor_sync(0xffffffffu, m1[q], d);
            int   bi1 = __shfl_xor_sync(0xffffffffu, i1[q], d);
            float bm2 = __shfl_xor_sync(0xffffffffu, m2[q], d);
            int   bi2 = __shfl_xor_sync(0xffffffffu, i2[q], d);
            float bm3 = __shfl_xor_sync(0xffffffffu, m3[q], d);
            merge3(m1[q], i1[q], m2[q], i2[q], m3[q], bm1, bi1, bm2, bi2, bm3);
        }
    }

    // cross-warp merge over wn (two warps share each row range)
    if (wn == 1 && (lane & 3) == 0) {
#pragma unroll
        for (int q = 0; q < 4; q++) {
            int r = wm * 32 + (q >> 1) * 16 + (q & 1) * 8 + (lane >> 2);
            pm1[r] = m1[q]; pm2[r] = m2[q]; pm3[r] = m3[q];
            pi1[r] = i1[q]; pi2[r] = i2[q];
        }
    }
    __syncthreads();
    if (wn == 0 && (lane & 3) == 0) {
#pragma unroll
        for (int q = 0; q < 4; q++) {
            int r = wm * 32 + (q >> 1) * 16 + (q & 1) * 8 + (lane >> 2);
            merge3(m1[q], i1[q], m2[q], i2[q], m3[q],
                   pm1[r], pi1[r], pm2[r], pi2[r], pm3[r]);
            int row = h * N_ + ntb * TM + r;
            g_idx[row] = i1[q];
            if (!(m2[q] - m1[q] > W_SEL)) {
                if (m3[q] - m1[q] > W_SEL) {
                    int p = atomicAdd(&g_cntA, 1);
                    g_listA[p] = row; g_listA2[p] = i2[q];
                } else {
                    int p = atomicAdd(&g_cntB, 1);
                    g_listB[p] = row;
                }
            }
        }
    }
}

// ---------------------------------------------------------------------------
// Candidate cleanup: exact (reference-order) compare of {i1, i2} per row
// ---------------------------------------------------------------------------
__global__ void cand_kernel(const float* __restrict__ x,
                            const float* __restrict__ ke) {
    int t = blockIdx.x * blockDim.x + threadIdx.x;
    int stride = gridDim.x * blockDim.x;
    for (int e = t; e < g_cntA; e += stride) {
        int row = g_listA[e];
        int c1 = g_idx[row];
        int c2 = g_listA2[e];
        int h = row >> 12, n = row & (N_ - 1);
        const float* xp = x + (size_t)n * DIM_ + h * DK_;
        const float* kp1 = ke + ((size_t)h * C_ + c1) * DK_;
        const float* kp2 = ke + ((size_t)h * C_ + c2) * DK_;
        float x2 = 0.f, d1 = 0.f, d2 = 0.f;
#pragma unroll
        for (int d = 0; d < DK_; d++) {
            float xv = __ldg(xp + d);
            x2 = __fmaf_rn(xv, xv, x2);
            d1 = __fmaf_rn(xv, __ldg(kp1 + d), d1);
            d2 = __fmaf_rn(xv, __ldg(kp2 + d), d2);
        }
        float s1 = __fadd_rn(__fmaf_rn(-2.f, d1, x2), g_e2[h * C_ + c1]);
        float s2 = __fadd_rn(__fmaf_rn(-2.f, d2, x2), g_e2[h * C_ + c2]);
        int w = (s2 < s1 || (s2 == s1 && c2 < c1)) ? c2 : c1;
        g_idx[row] = w;
    }
}

// ---------------------------------------------------------------------------
// Full replay (rare rows): exact fp32, smem-staged coalesced
// block = 128; one row per block (grid-stride)
// ---------------------------------------------------------------------------
__global__ void replay_kernel(const float* __restrict__ x,
                              const float* __restrict__ ke) {
    __shared__ float kt[128 * 65];
    __shared__ float xsr[DK_];
    __shared__ float rv[128];
    __shared__ int   ri[128];
    const int tid = threadIdx.x;
    for (int e = blockIdx.x; e < g_cntB; e += gridDim.x) {
        int row = g_listB[e];
        int h = row >> 12, n = row & (N_ - 1);
        if (tid < DK_) xsr[tid] = x[(size_t)n * DIM_ + h * DK_ + tid];
        __syncthreads();
        float x2 = 0.f;
#pragma unroll
        for (int d = 0; d < DK_; d++) x2 = __fmaf_rn(xsr[d], xsr[d], x2);
        const float* keh = ke + (size_t)h * C_ * DK_;
        const float* e2h = g_e2 + h * C_;
        float bv = CUDART_INF_F; int bi = 0;
        for (int tile = 0; tile < C_ / 128; tile++) {
            const float* kb = keh + (size_t)tile * 128 * DK_;
            // coalesced stage: 128 codes x 64 floats
#pragma unroll 4
            for (int m = tid; m < 128 * 16; m += 128) {
                int r = m >> 4, c4 = m & 15;
                float4 v = *(const float4*)(kb + (size_t)r * DK_ + c4 * 4);
                kt[r * 65 + c4 * 4 + 0] = v.x;
                kt[r * 65 + c4 * 4 + 1] = v.y;
                kt[r * 65 + c4 * 4 + 2] = v.z;
                kt[r * 65 + c4 * 4 + 3] = v.w;
            }
            __syncthreads();
            float dot = 0.f;
#pragma unroll
            for (int d = 0; d < DK_; d++) dot = __fmaf_rn(xsr[d], kt[tid * 65 + d], dot);
            float s = __fadd_rn(__fmaf_rn(-2.f, dot, x2), e2h[tile * 128 + tid]);
            int c = tile * 128 + tid;
            if (s < bv) { bv = s; bi = c; }
            __syncthreads();
        }
        rv[tid] = bv; ri[tid] = bi;
        __syncthreads();
        if (tid == 0) {
            float b = rv[0]; int bix = ri[0];
            for (int t = 1; t < 128; t++) {
                float v = rv[t]; int c = ri[t];
                if (v < b || (v == b && c < bix)) { b = v; bix = c; }
            }
            g_idx[row] = bix;
        }
        __syncthreads();
    }
}

// ---------------------------------------------------------------------------
// Gather
// ---------------------------------------------------------------------------
__global__ void gather_kernel(const float* __restrict__ vals,
                              float* __restrict__ out) {
    int lin = blockIdx.x * blockDim.x + threadIdx.x;   // H*N*16 float4s
    if (lin >= H_ * N_ * 16) return;
    int v4 = lin & 15; int hn = lin >> 4;
    int n = hn & (N_ - 1); int h = hn >> 12;
    int c = g_idx[hn];
    float4 v = *(const float4*)(vals + ((size_t)h * C_ + c) * DV_ + v4 * 4);
    *(float4*)(out + (size_t)n * DIM_ + h * DV_ + v4 * 4) = v;
}

// ---------------------------------------------------------------------------
extern "C" void kernel_launch(void* const* d_in, const int* in_sizes, int n_in,
                              void* d_out, int out_size) {
    const float* x    = (const float*)d_in[0];
    const float* ke   = (const float*)d_in[2];
    const float* vals = (const float*)d_in[3];
    float* out = (float*)d_out;

    cudaFuncSetAttribute(hmma_argmin_kernel,
                         cudaFuncAttributeMaxDynamicSharedMemorySize, SMEM_SZ);

    e2_kernel<<<(H_ * C_ + 255) / 256, 256>>>(ke);
    prep_a<<<(H_ * N_ * DK_) / 256, 256>>>(x);
    prep_b<<<(H_ * C_ * DK_) / 256, 256>>>(ke);

    dim3 grid(N_ / TM, H_);
    hmma_argmin_kernel<<<grid, 256, SMEM_SZ>>>();

    cand_kernel<<<64, 128>>>(x, ke);
    replay_kernel<<<64, 128>>>(x, ke);
    gather_kernel<<<(H_ * N_ * 16) / 256, 256>>>(vals, out);
}

// round 6
// speedup vs baseline: 4.3925x; 1.2849x over previous
#include <cuda_runtime.h>
#include <cuda_bf16.h>
#include <math_constants.h>
#include <stdint.h>

// Problem dims
#define B_   4
#define T_   1024
#define H_   12
#define C_   4096
#define DK_  64
#define DV_  64
#define N_   (B_*T_)      // 4096
#define DIM_ (H_*DK_)     // 768

// GEMM config
#define KP   192          // packed K (bf16 split: [xh|xh|xl] . [eh|el|eh])
#define TM   128          // rows per CTA
#define TCC  64           // codes per iteration
#define NCT  (C_/TCC)     // 64
#define SA   400          // smem row stride bytes (conflict-free ldmatrix)
#define B_TILE_BYTES (TCC*SA)     // 25600
#define W_SEL 3e-4f       // ambiguity window (>= ~10x approx-error bound)

// smem offsets (main kernel)
#define OFF_A   0
#define OFF_B   51200             // 2 buffers of B
#define OFF_P   102400            // pm1,pm2,pm3,pi1,pi2 : 5 * 128 * 4
#define SMEM_SZ 104960

// Device scratch
__device__ __align__(1024) __nv_bfloat16 g_B[(size_t)H_*C_*KP];
__device__ float g_e2[H_*C_];
__device__ int   g_idx[H_*N_];
__device__ int   g_listB[H_*N_];   // full-replay rows (both gaps ambiguous)
__device__ int   g_cntB;

// ---------------- helpers ----------------
__device__ __forceinline__ uint32_t smem_u32(const void* p) {
    uint32_t a;
    asm("{ .reg .u64 t; cvta.to.shared.u64 t, %1; cvt.u32.u64 %0, t; }" : "=r"(a) : "l"(p));
    return a;
}
__device__ __forceinline__ void cpa16(uint32_t dst, const void* src) {
    asm volatile("cp.async.cg.shared.global [%0], [%1], 16;" :: "r"(dst), "l"(src));
}
__device__ __forceinline__ void cpa_commit() { asm volatile("cp.async.commit_group;" ::: "memory"); }
__device__ __forceinline__ void cpa_wait0()  { asm volatile("cp.async.wait_group 0;" ::: "memory"); }
__device__ __forceinline__ void cpa_wait1()  { asm volatile("cp.async.wait_group 1;" ::: "memory"); }

__device__ __forceinline__ void ldsm4(uint32_t* r, uint32_t addr) {
    asm volatile("ldmatrix.sync.aligned.m8n8.x4.shared.b16 {%0,%1,%2,%3}, [%4];"
                 : "=r"(r[0]), "=r"(r[1]), "=r"(r[2]), "=r"(r[3]) : "r"(addr));
}
__device__ __forceinline__ void mma16816(float* d, const uint32_t* a, const uint32_t* b) {
    asm volatile("mma.sync.aligned.m16n8k16.row.col.f32.bf16.bf16.f32 "
                 "{%0,%1,%2,%3}, {%4,%5,%6,%7}, {%8,%9}, {%0,%1,%2,%3};"
                 : "+f"(d[0]), "+f"(d[1]), "+f"(d[2]), "+f"(d[3])
                 : "r"(a[0]), "r"(a[1]), "r"(a[2]), "r"(a[3]), "r"(b[0]), "r"(b[1]));
}

// merge two top-3 partial states (values m1<=m2<=m3, indices for m1,m2)
__device__ __forceinline__ void merge3(float& m1, int& i1, float& m2, int& i2, float& m3,
                                       float bm1, int bi1, float bm2, int bi2, float bm3) {
    if (bm1 < m1 || (bm1 == m1 && bi1 < i1)) {
        float t; int ti;
        t = m1; m1 = bm1; bm1 = t;  ti = i1; i1 = bi1; bi1 = ti;
        t = m2; m2 = bm2; bm2 = t;  ti = i2; i2 = bi2; bi2 = ti;
        t = m3; m3 = bm3; bm3 = t;
    }
    if (bm1 < m2 || (bm1 == m2 && bi1 < i2)) {
        m3 = fminf(m2, bm2);
        m2 = bm1; i2 = bi1;
    } else {
        m3 = fminf(m3, bm1);
    }
}

// ---------------------------------------------------------------------------
// Fused prep: e2 (exact sequential order) + B split-pack, smem-staged coalesced
// grid = H*C/64 blocks of 256; each block: 64 ke rows
// ---------------------------------------------------------------------------
__global__ void prep_be2_kernel(const float* __restrict__ ke) {
    __shared__ float kt[64 * 65];
    const int tid = threadIdx.x;
    const int row0 = blockIdx.x * 64;          // within H*C
    if (blockIdx.x == 0 && tid == 0) g_cntB = 0;

    // coalesced stage: 64 rows x 64 floats
#pragma unroll 4
    for (int m = tid; m < 64 * 16; m += 256) {
        int r = m >> 4, c4 = m & 15;
        float4 v = *(const float4*)(ke + (size_t)(row0 + r) * DK_ + c4 * 4);
        kt[r * 65 + c4 * 4 + 0] = v.x;
        kt[r * 65 + c4 * 4 + 1] = v.y;
        kt[r * 65 + c4 * 4 + 2] = v.z;
        kt[r * 65 + c4 * 4 + 3] = v.w;
    }
    __syncthreads();

    // e2: one row per thread (first 64 threads), sequential fma order
    if (tid < 64) {
        float s = 0.f;
#pragma unroll
        for (int d = 0; d < DK_; d++) {
            float v = kt[tid * 65 + d];
            s = __fmaf_rn(v, v, s);
        }
        g_e2[row0 + tid] = s;
    }

    // split-pack: row layout [eh(64) | el(64) | eh(64)], bf16x2 writes
#pragma unroll 4
    for (int m = tid; m < 64 * 32; m += 256) {
        int r = m >> 5, dp = m & 31;
        float v0 = kt[r * 65 + dp * 2], v1 = kt[r * 65 + dp * 2 + 1];
        __nv_bfloat16 h0 = __float2bfloat16(v0);
        __nv_bfloat16 l0 = __float2bfloat16(v0 - __bfloat162float(h0));
        __nv_bfloat16 h1 = __float2bfloat16(v1);
        __nv_bfloat16 l1 = __float2bfloat16(v1 - __bfloat162float(h1));
        __nv_bfloat162 hh; hh.x = h0; hh.y = h1;
        __nv_bfloat162 ll; ll.x = l0; ll.y = l1;
        __nv_bfloat16* base = g_B + (size_t)(row0 + r) * KP;
        *(__nv_bfloat162*)(base + dp * 2)        = hh;
        *(__nv_bfloat162*)(base + 64 + dp * 2)   = ll;
        *(__nv_bfloat162*)(base + 128 + dp * 2)  = hh;
    }
}

// ---------------------------------------------------------------------------
// Main: in-kernel A split + bf16 HMMA GEMM (K=192) + top-3 argmin
//       + inline exact 2-candidate resolution
// grid = (N_/TM, H_), block = 256 (8 warps, 4(wm) x 2(wn), warp tile 32x32)
// ---------------------------------------------------------------------------
__global__ __launch_bounds__(256, 2)
void hmma_argmin_kernel(const float* __restrict__ x,
                        const float* __restrict__ ke) {
    extern __shared__ char smem[];
    const uint32_t sb = smem_u32(smem);
    const int tid = threadIdx.x, lane = tid & 31, wid = tid >> 5;
    const int wm = wid >> 1, wn = wid & 1;
    const int h = blockIdx.y, ntb = blockIdx.x;

    float* pm1 = (float*)(smem + OFF_P);
    float* pm2 = pm1 + 128;
    float* pm3 = pm2 + 128;
    int*   pi1 = (int*)(pm3 + 128);
    int*   pi2 = pi1 + 128;

    const __nv_bfloat16* Bg = g_B + (size_t)h * C_ * KP;
    const float* e2h = g_e2 + h * C_;

    // Prologue: B tile 0 via cp.async; A tile converted in-kernel from x
#pragma unroll 2
    for (int m = tid; m < TCC * 24; m += 256)
        cpa16(sb + OFF_B + (m / 24) * SA + (m % 24) * 16, Bg + m * 8);
    cpa_commit();

    {
        const float* xb = x + (size_t)(ntb * TM) * DIM_ + h * DK_;
#pragma unroll 4
        for (int m = tid; m < TM * 32; m += 256) {
            int r = m >> 5, dp = m & 31;
            float2 v = *(const float2*)(xb + (size_t)r * DIM_ + dp * 2);
            __nv_bfloat16 h0 = __float2bfloat16(v.x);
            __nv_bfloat16 l0 = __float2bfloat16(v.x - __bfloat162float(h0));
            __nv_bfloat16 h1 = __float2bfloat16(v.y);
            __nv_bfloat16 l1 = __float2bfloat16(v.y - __bfloat162float(h1));
            __nv_bfloat162 hh; hh.x = h0; hh.y = h1;
            __nv_bfloat162 ll; ll.x = l0; ll.y = l1;
            char* arow = smem + OFF_A + r * SA;          // [xh | xh | xl]
            *(__nv_bfloat162*)(arow + dp * 4)        = hh;
            *(__nv_bfloat162*)(arow + 128 + dp * 4)  = hh;
            *(__nv_bfloat162*)(arow + 256 + dp * 4)  = ll;
        }
    }

    // ldmatrix base addresses (warp tile 32 rows x 32 cols)
    const uint32_t aAddr = sb + OFF_A +
        (uint32_t)((wm * 32 + (lane & 15)) * SA + (lane >> 4) * 16);
    const uint32_t bAddrBase =
        (uint32_t)((wn * 32 + (lane & 7) + ((lane >> 4) & 1) * 8) * SA +
                   ((lane >> 3) & 1) * 16);

    float m1[4], m2[4], m3[4]; int i1[4], i2[4];
#pragma unroll
    for (int q = 0; q < 4; q++) {
        m1[q] = CUDART_INF_F; m2[q] = CUDART_INF_F; m3[q] = CUDART_INF_F;
        i1[q] = 0; i2[q] = 0;
    }

    for (int ct = 0; ct < NCT; ct++) {
        if (ct + 1 < NCT) {
            const __nv_bfloat16* Bt = Bg + (size_t)(ct + 1) * TCC * KP;
            uint32_t dstb = sb + OFF_B + ((ct + 1) & 1) * B_TILE_BYTES;
#pragma unroll 2
            for (int m = tid; m < TCC * 24; m += 256)
                cpa16(dstb + (m / 24) * SA + (m % 24) * 16, Bt + m * 8);
            cpa_commit();
            cpa_wait1();
        } else {
            cpa_wait0();
        }
        __syncthreads();

        const int cth = ct * TCC + wn * 32 + (lane & 3) * 2;
        float e2v[4][2];
#pragma unroll
        for (int nt = 0; nt < 4; nt++) {
            e2v[nt][0] = __ldg(e2h + cth + nt * 8);
            e2v[nt][1] = __ldg(e2h + cth + nt * 8 + 1);
        }

        float acc[2][4][4];
#pragma unroll
        for (int mt = 0; mt < 2; mt++)
#pragma unroll
            for (int nt = 0; nt < 4; nt++)
#pragma unroll
                for (int v = 0; v < 4; v++) acc[mt][nt][v] = 0.f;

        const uint32_t bAddr = sb + OFF_B + (ct & 1) * B_TILE_BYTES + bAddrBase;

#pragma unroll
        for (int ks = 0; ks < 12; ks++) {
            uint32_t a[2][4], b[2][4];
#pragma unroll
            for (int mt = 0; mt < 2; mt++)
                ldsm4(a[mt], aAddr + mt * (16 * SA) + ks * 32);
#pragma unroll
            for (int np = 0; np < 2; np++)
                ldsm4(b[np], bAddr + np * (16 * SA) + ks * 32);
#pragma unroll
            for (int mt = 0; mt < 2; mt++)
#pragma unroll
                for (int nt = 0; nt < 4; nt++)
                    mma16816(acc[mt][nt], a[mt], &b[nt >> 1][(nt & 1) * 2]);
        }

        // epilogue: fast-path compare vs m3; rare full top-3 insert
#pragma unroll
        for (int mt = 0; mt < 2; mt++)
#pragma unroll
            for (int nt = 0; nt < 4; nt++)
#pragma unroll
                for (int v = 0; v < 4; v++) {
                    float s = fmaf(-2.f, acc[mt][nt][v], e2v[nt][v & 1]);
                    int q = mt * 2 + (v >> 1);
                    if (s < m3[q]) {                 // rare after warmup
                        int c = cth + nt * 8 + (v & 1);
                        if (s < m1[q]) {
                            m3[q] = m2[q]; m2[q] = m1[q]; i2[q] = i1[q];
                            m1[q] = s; i1[q] = c;
                        } else if (s < m2[q]) {
                            m3[q] = m2[q]; m2[q] = s; i2[q] = c;
                        } else {
                            m3[q] = s;
                        }
                    }
                }
        __syncthreads();
    }

    // quad reduce (lanes xor 1,2 cover disjoint columns, same rows)
#pragma unroll
    for (int q = 0; q < 4; q++) {
#pragma unroll
        for (int d = 1; d <= 2; d <<= 1) {
            float bm1 = __shfl_xor_sync(0xffffffffu, m1[q], d);
            int   bi1 = __shfl_xor_sync(0xffffffffu, i1[q], d);
            float bm2 = __shfl_xor_sync(0xffffffffu, m2[q], d);
            int   bi2 = __shfl_xor_sync(0xffffffffu, i2[q], d);
            float bm3 = __shfl_xor_sync(0xffffffffu, m3[q], d);
            merge3(m1[q], i1[q], m2[q], i2[q], m3[q], bm1, bi1, bm2, bi2, bm3);
        }
    }

    // cross-warp merge over wn
    if (wn == 1 && (lane & 3) == 0) {
#pragma unroll
        for (int q = 0; q < 4; q++) {
            int r = wm * 32 + (q >> 1) * 16 + (q & 1) * 8 + (lane >> 2);
            pm1[r] = m1[q]; pm2[r] = m2[q]; pm3[r] = m3[q];
            pi1[r] = i1[q]; pi2[r] = i2[q];
        }
    }
    __syncthreads();
    if (wn == 0 && (lane & 3) == 0) {
#pragma unroll
        for (int q = 0; q < 4; q++) {
            int r = wm * 32 + (q >> 1) * 16 + (q & 1) * 8 + (lane >> 2);
            merge3(m1[q], i1[q], m2[q], i2[q], m3[q],
                   pm1[r], pi1[r], pm2[r], pi2[r], pm3[r]);
            int n   = ntb * TM + r;
            int row = h * N_ + n;
            g_idx[row] = i1[q];
            if (!(m2[q] - m1[q] > W_SEL)) {
                if (m3[q] - m1[q] > W_SEL) {
                    // winner provably in {i1, i2}: exact reference-order compare
                    int c1 = i1[q], c2 = i2[q];
                    const float* xp  = x  + (size_t)n * DIM_ + h * DK_;
                    const float* kp1 = ke + ((size_t)h * C_ + c1) * DK_;
                    const float* kp2 = ke + ((size_t)h * C_ + c2) * DK_;
                    float x2 = 0.f, d1 = 0.f, d2 = 0.f;
#pragma unroll
                    for (int d = 0; d < DK_; d++) {
                        float xv = __ldg(xp + d);
                        x2 = __fmaf_rn(xv, xv, x2);
                        d1 = __fmaf_rn(xv, __ldg(kp1 + d), d1);
                        d2 = __fmaf_rn(xv, __ldg(kp2 + d), d2);
                    }
                    float s1 = __fadd_rn(__fmaf_rn(-2.f, d1, x2), e2h[c1]);
                    float s2 = __fadd_rn(__fmaf_rn(-2.f, d2, x2), e2h[c2]);
                    g_idx[row] = (s2 < s1 || (s2 == s1 && c2 < c1)) ? c2 : c1;
                } else {
                    int p = atomicAdd(&g_cntB, 1);
                    g_listB[p] = row;
                }
            }
        }
    }
}

// ---------------------------------------------------------------------------
// Full replay (rare rows): exact fp32, smem-staged coalesced
// ---------------------------------------------------------------------------
__global__ void replay_kernel(const float* __restrict__ x,
                              const float* __restrict__ ke) {
    __shared__ float kt[128 * 65];
    __shared__ float xsr[DK_];
    __shared__ float rv[128];
    __shared__ int   ri[128];
    const int tid = threadIdx.x;
    for (int e = blockIdx.x; e < g_cntB; e += gridDim.x) {
        int row = g_listB[e];
        int h = row >> 12, n = row & (N_ - 1);
        if (tid < DK_) xsr[tid] = x[(size_t)n * DIM_ + h * DK_ + tid];
        __syncthreads();
        float x2 = 0.f;
#pragma unroll
        for (int d = 0; d < DK_; d++) x2 = __fmaf_rn(xsr[d], xsr[d], x2);
        const float* keh = ke + (size_t)h * C_ * DK_;
        const float* e2h = g_e2 + h * C_;
        float bv = CUDART_INF_F; int bi = 0;
        for (int tile = 0; tile < C_ / 128; tile++) {
            const float* kb = keh + (size_t)tile * 128 * DK_;
#pragma unroll 4
            for (int m = tid; m < 128 * 16; m += 128) {
                int r = m >> 4, c4 = m & 15;
                float4 v = *(const float4*)(kb + (size_t)r * DK_ + c4 * 4);
                kt[r * 65 + c4 * 4 + 0] = v.x;
                kt[r * 65 + c4 * 4 + 1] = v.y;
                kt[r * 65 + c4 * 4 + 2] = v.z;
                kt[r * 65 + c4 * 4 + 3] = v.w;
            }
            __syncthreads();
            float dot = 0.f;
#pragma unroll
            for (int d = 0; d < DK_; d++) dot = __fmaf_rn(xsr[d], kt[tid * 65 + d], dot);
            float s = __fadd_rn(__fmaf_rn(-2.f, dot, x2), e2h[tile * 128 + tid]);
            int c = tile * 128 + tid;
            if (s < bv) { bv = s; bi = c; }
            __syncthreads();
        }
        rv[tid] = bv; ri[tid] = bi;
        __syncthreads();
        if (tid == 0) {
            float b = rv[0]; int bix = ri[0];
            for (int t = 1; t < 128; t++) {
                float v = rv[t]; int c = ri[t];
                if (v < b || (v == b && c < bix)) { b = v; bix = c; }
            }
            g_idx[row] = bix;
        }
        __syncthreads();
    }
}

// ---------------------------------------------------------------------------
// Gather
// ---------------------------------------------------------------------------
__global__ void gather_kernel(const float* __restrict__ vals,
                              float* __restrict__ out) {
    int lin = blockIdx.x * blockDim.x + threadIdx.x;   // H*N*16 float4s
    if (lin >= H_ * N_ * 16) return;
    int v4 = lin & 15; int hn = lin >> 4;
    int n = hn & (N_ - 1); int h = hn >> 12;
    int c = g_idx[hn];
    float4 v = *(const float4*)(vals + ((size_t)h * C_ + c) * DV_ + v4 * 4);
    *(float4*)(out + (size_t)n * DIM_ + h * DV_ + v4 * 4) = v;
}

// ---------------------------------------------------------------------------
extern "C" void kernel_launch(void* const* d_in, const int* in_sizes, int n_in,
                              void* d_out, int out_size) {
    const float* x    = (const float*)d_in[0];
    const float* ke   = (const float*)d_in[2];
    const float* vals = (const float*)d_in[3];
    float* out = (float*)d_out;

    cudaFuncSetAttribute(hmma_argmin_kernel,
                         cudaFuncAttributeMaxDynamicSharedMemorySize, SMEM_SZ);

    prep_be2_kernel<<<H_ * C_ / 64, 256>>>(ke);

    dim3 grid(N_ / TM, H_);
    hmma_argmin_kernel<<<grid, 256, SMEM_SZ>>>(x, ke);

    replay_kernel<<<64, 128>>>(x, ke);
    gather_kernel<<<(H_ * N_ * 16) / 256, 256>>>(vals, out);
}